// round 2
// baseline (speedup 1.0000x reference)
#include <cuda_runtime.h>

// Involution2d: B=8, C=256, G=4, Cpg=64, K=7, H=W=Ho=Wo=64, pad=3, stride=1, dil=1
// out[b,c,ho,wo] = sum_{kh,kw} in[b,c,ho+kh-3,wo+kw-3] * w[b,g,kh,kw,ho,wo] + bias[c]
//
// Strategy:
//  - weights for this thread's 2 output pixels live in 98 registers, reused
//    across all 64 channels of the group (weight read exactly once from HBM)
//  - input tile (14 x 38, halo=3) staged in shared memory per channel
//  - TH=2 output rows per thread: each 7-wide smem row read feeds both
//    accumulators -> 28 LDS per output instead of 49
//  - software pipeline: next channel's global loads are issued (into regs)
//    before computing the current channel from smem

#define TILE_W 32
#define TILE_H 8
#define SH (TILE_H + 6)      // 14
#define SW (TILE_W + 6)      // 38
#define SWP 40               // padded row stride
#define NSTAGE 5             // ceil(14*38 / 128)

__global__ __launch_bounds__(128, 3)
void involution2d_kernel(const float* __restrict__ input,
                         const float* __restrict__ weight,
                         const float* __restrict__ bias,
                         float* __restrict__ out)
{
    __shared__ float tile[SH * SWP];

    const int tx  = threadIdx.x;          // 0..31  (wo within tile)
    const int ty  = threadIdx.y;          // 0..3   (output row-pair)
    const int tid = ty * 32 + tx;

    int bid = blockIdx.x;
    const int wt = bid & 1;  bid >>= 1;   // 2 tiles across W
    const int ht = bid & 7;  bid >>= 3;   // 8 tiles across H
    const int g  = bid & 3;  bid >>= 2;   // 4 groups
    const int b  = bid;                   // 8 batches

    const int w0g = wt * TILE_W;
    const int h0g = ht * TILE_H;

    const int oy0 = ty * 2;               // tile-relative output rows oy0, oy0+1
    const int ho0 = h0g + oy0;
    const int wo  = w0g + tx;

    // ---- load 2x49 weights into registers (read once per thread, ever) ----
    // weight[b,g,kh,kw,ho,wo]: stride per (kh,kw) tap = 64*64 = 4096
    float wr0[49], wr1[49];
    {
        const float* wp0 = weight + ((b * 4 + g) * 49) * 4096 + ho0 * 64 + wo;
        const float* wp1 = wp0 + 64;
        #pragma unroll
        for (int k = 0; k < 49; ++k) {
            wr0[k] = wp0[k * 4096];
            wr1[k] = wp1[k * 4096];
        }
    }

    // ---- precompute staged-load addressing (constant across channels) ----
    const float* inb  = input + (b * 256 + g * 64) * 4096;
    float*       outb = out   + (b * 256 + g * 64) * 4096;

    int  goff[NSTAGE];   // global offset within a channel plane
    int  sidx[NSTAGE];   // smem destination index
    bool okm [NSTAGE];   // in-bounds (incl. zero-pad) mask
    #pragma unroll
    for (int k = 0; k < NSTAGE; ++k) {
        int i  = tid + k * 128;
        int r  = i / SW;
        int cc = i - r * SW;
        int gh = h0g - 3 + r;
        int gw = w0g - 3 + cc;
        bool valid = (i < SH * SW);
        bool inb_ok = ((unsigned)gh < 64u) && ((unsigned)gw < 64u);
        okm [k] = valid && inb_ok;
        goff[k] = okm[k] ? (gh * 64 + gw) : 0;
        sidx[k] = valid ? (r * SWP + cc) : 0;
        if (!valid) sidx[k] = SH * SWP - 1;  // harmless duplicate slot
    }

    // ---- prime pipeline: stage channel 0 into registers ----
    float st[NSTAGE];
    #pragma unroll
    for (int k = 0; k < NSTAGE; ++k)
        st[k] = okm[k] ? inb[goff[k]] : 0.0f;

    for (int ch = 0; ch < 64; ++ch) {
        __syncthreads();                         // smem free from prev compute
        #pragma unroll
        for (int k = 0; k < NSTAGE; ++k)
            tile[sidx[k]] = st[k];
        __syncthreads();                         // tile ready

        // issue next channel's global loads; they complete during compute
        if (ch + 1 < 64) {
            const float* inc = inb + (ch + 1) * 4096;
            #pragma unroll
            for (int k = 0; k < NSTAGE; ++k)
                st[k] = okm[k] ? inc[goff[k]] : 0.0f;
        }

        // ---- compute 2 output rows from the smem tile ----
        float acc0 = 0.0f, acc1 = 0.0f;
        #pragma unroll
        for (int r = 0; r < 8; ++r) {
            float x[7];
            const float* row = &tile[(oy0 + r) * SWP + tx];
            #pragma unroll
            for (int j = 0; j < 7; ++j)
                x[j] = row[j];
            if (r < 7) {
                #pragma unroll
                for (int j = 0; j < 7; ++j)
                    acc0 += x[j] * wr0[r * 7 + j];
            }
            if (r >= 1) {
                #pragma unroll
                for (int j = 0; j < 7; ++j)
                    acc1 += x[j] * wr1[(r - 1) * 7 + j];
            }
        }

        const float bv = bias[g * 64 + ch];
        float* op = outb + ch * 4096 + ho0 * 64 + wo;
        op[0]  = acc0 + bv;
        op[64] = acc1 + bv;
    }
}

extern "C" void kernel_launch(void* const* d_in, const int* in_sizes, int n_in,
                              void* d_out, int out_size)
{
    const float* input  = (const float*)d_in[0];
    const float* weight = (const float*)d_in[1];
    const float* bias   = (const float*)d_in[2];
    float*       out    = (float*)d_out;

    dim3 block(32, 4, 1);
    dim3 grid(8 * 4 * 8 * 2, 1, 1);   // B * G * Htiles * Wtiles = 512
    involution2d_kernel<<<grid, block>>>(input, weight, bias, out);
}

// round 3
// speedup vs baseline: 1.4009x; 1.4009x over previous
#include <cuda_runtime.h>

// Involution2d: B=8, C=256, G=4, Cpg=64, K=7, H=W=64, pad=3
// out[b,c,ho,wo] = sum_{kh,kw} in[b,c,ho+kh-3,wo+kw-3] * w[b,g,kh,kw,ho,wo] + bias[c]
//
// R2 changes vs R1 (84us):
//  - 4 CTAs/SM (regs<=128 via launch_bounds) -> 512 CTAs = ONE wave on 148 SMs
//  - cp.async double-buffered smem, 2 channels per stage, 1 barrier / 2 channels
//  - halo zeroed once (constant across channels), cp.async only in-bounds cells
//  - bias staged in smem

#define TILE_W 32
#define TILE_H 8
#define SH 14                 // TILE_H + 6
#define SW 38                 // TILE_W + 6
#define SWP 40                // padded row stride (floats)
#define PLANE (SH*SWP)        // 560 floats per channel plane
#define NSTAGE 5              // ceil(SH*SW / 128)
#define STAGE_CH 2            // channels per pipeline stage
#define NSTAGES 32            // 64 / STAGE_CH

__device__ __forceinline__ void cpa4(unsigned dst, const float* src) {
    asm volatile("cp.async.ca.shared.global [%0], [%1], 4;\n" :: "r"(dst), "l"(src));
}
__device__ __forceinline__ void cpa_commit() {
    asm volatile("cp.async.commit_group;\n" ::: "memory");
}
__device__ __forceinline__ void cpa_wait_all() {
    asm volatile("cp.async.wait_group 0;\n" ::: "memory");
}

__global__ __launch_bounds__(128, 4)
void involution2d_kernel(const float* __restrict__ input,
                         const float* __restrict__ weight,
                         const float* __restrict__ bias,
                         float* __restrict__ out)
{
    __shared__ float tile[2 * STAGE_CH * PLANE];   // double-buffered 2-ch stage
    __shared__ float sbias[64];

    const int tx  = threadIdx.x;            // 0..31
    const int ty  = threadIdx.y;            // 0..3
    const int tid = ty * 32 + tx;

    int bid = blockIdx.x;
    const int wt = bid & 1;  bid >>= 1;
    const int ht = bid & 7;  bid >>= 3;
    const int g  = bid & 3;  bid >>= 2;
    const int b  = bid;

    const int w0g = wt * TILE_W;
    const int h0g = ht * TILE_H;
    const int oy0 = ty * 2;
    const int ho0 = h0g + oy0;
    const int wo  = w0g + tx;

    if (tid < 64) sbias[tid] = bias[g * 64 + tid];

    // ---- weights for this thread's 2 output rows: 98 regs, read once ----
    float wr0[49], wr1[49];
    {
        const float* wp = weight + ((size_t)(b * 4 + g) * 49) * 4096 + ho0 * 64 + wo;
        #pragma unroll
        for (int k = 0; k < 49; ++k) {
            wr0[k] = wp[k * 4096];
            wr1[k] = wp[k * 4096 + 64];
        }
    }

    const float* inb  = input + (b * 256 + g * 64) * 4096;
    float*       outb = out   + (b * 256 + g * 64) * 4096;

    // ---- staged-load addressing (constant across channels) ----
    unsigned sdst[NSTAGE];
    int      goff[NSTAGE];
    bool     okm [NSTAGE];
    const unsigned sbase = (unsigned)__cvta_generic_to_shared(&tile[0]);
    #pragma unroll
    for (int k = 0; k < NSTAGE; ++k) {
        int i  = tid + k * 128;
        int r  = i / SW;
        int cc = i - r * SW;
        int gh = h0g - 3 + r;
        int gw = w0g - 3 + cc;
        bool valid = (i < SH * SW);
        bool ib    = ((unsigned)gh < 64u) && ((unsigned)gw < 64u);
        okm [k] = valid && ib;
        goff[k] = gh * 64 + gw;
        sdst[k] = sbase + (unsigned)(r * SWP + cc) * 4u;
        if (valid && !ib) {
            // halo: constant zero across all channels; write once, all planes
            #pragma unroll
            for (int p = 0; p < 2 * STAGE_CH; ++p)
                tile[p * PLANE + r * SWP + cc] = 0.0f;
        }
    }

    const unsigned BUFB = (unsigned)(STAGE_CH * PLANE * 4);  // bytes per buffer

    // ---- prologue: stage 0 -> buffer 0 ----
    #pragma unroll
    for (int c = 0; c < STAGE_CH; ++c)
        #pragma unroll
        for (int k = 0; k < NSTAGE; ++k)
            if (okm[k]) cpa4(sdst[k] + c * (PLANE * 4), inb + c * 4096 + goff[k]);
    cpa_commit();

    for (int s = 0; s < NSTAGES; ++s) {
        cpa_wait_all();          // stage s data landed (own ops)
        __syncthreads();         // all threads: data visible + prev compute done

        // issue stage s+1 into the other buffer (overlaps with compute below)
        if (s + 1 < NSTAGES) {
            const float* gsrc = inb + (size_t)(s + 1) * (STAGE_CH * 4096);
            const unsigned bo = ((s + 1) & 1) * BUFB;
            #pragma unroll
            for (int c = 0; c < STAGE_CH; ++c)
                #pragma unroll
                for (int k = 0; k < NSTAGE; ++k)
                    if (okm[k]) cpa4(sdst[k] + bo + c * (PLANE * 4), gsrc + c * 4096 + goff[k]);
        }
        cpa_commit();

        // ---- compute the 2 channels of stage s ----
        const float* bufp = &tile[(s & 1) * STAGE_CH * PLANE];
        #pragma unroll
        for (int c = 0; c < STAGE_CH; ++c) {
            const float* plane = bufp + c * PLANE;
            float acc0 = 0.0f, acc1 = 0.0f;
            #pragma unroll
            for (int r = 0; r < 8; ++r) {
                float x[7];
                const float* row = plane + (oy0 + r) * SWP + tx;
                #pragma unroll
                for (int j = 0; j < 7; ++j) x[j] = row[j];
                if (r < 7) {
                    #pragma unroll
                    for (int j = 0; j < 7; ++j) acc0 += x[j] * wr0[r * 7 + j];
                }
                if (r >= 1) {
                    #pragma unroll
                    for (int j = 0; j < 7; ++j) acc1 += x[j] * wr1[(r - 1) * 7 + j];
                }
            }
            const int ch = s * STAGE_CH + c;
            const float bv = sbias[ch];
            float* op = outb + ch * 4096 + ho0 * 64 + wo;
            op[0]  = acc0 + bv;
            op[64] = acc1 + bv;
        }
    }
}

extern "C" void kernel_launch(void* const* d_in, const int* in_sizes, int n_in,
                              void* d_out, int out_size)
{
    const float* input  = (const float*)d_in[0];
    const float* weight = (const float*)d_in[1];
    const float* bias   = (const float*)d_in[2];
    float*       out    = (float*)d_out;

    dim3 block(32, 4, 1);
    dim3 grid(8 * 4 * 8 * 2, 1, 1);   // B * G * Htiles * Wtiles = 512
    involution2d_kernel<<<grid, block>>>(input, weight, bias, out);
}

// round 4
// speedup vs baseline: 1.4505x; 1.0354x over previous
#include <cuda_runtime.h>

// Involution2d: B=8, C=256, G=4, Cpg=64, K=7, H=W=64, pad=3
// out[b,c,ho,wo] = sum_{kh,kw} in[b,c,ho+kh-3,wo+kw-3] * w[b,g,kh,kw,ho,wo] + bias[c]
//
// R2 changes vs R1 (84us):
//  - 4 CTAs/SM (regs<=128 via launch_bounds) -> 512 CTAs = ONE wave on 148 SMs
//  - cp.async double-buffered smem, 2 channels per stage, 1 barrier / 2 channels
//  - halo zeroed once (constant across channels), cp.async only in-bounds cells
//  - bias staged in smem

#define TILE_W 32
#define TILE_H 8
#define SH 14                 // TILE_H + 6
#define SW 38                 // TILE_W + 6
#define SWP 40                // padded row stride (floats)
#define PLANE (SH*SWP)        // 560 floats per channel plane
#define NSTAGE 5              // ceil(SH*SW / 128)
#define STAGE_CH 2            // channels per pipeline stage
#define NSTAGES 32            // 64 / STAGE_CH

__device__ __forceinline__ void cpa4(unsigned dst, const float* src) {
    asm volatile("cp.async.ca.shared.global [%0], [%1], 4;\n" :: "r"(dst), "l"(src));
}
__device__ __forceinline__ void cpa_commit() {
    asm volatile("cp.async.commit_group;\n" ::: "memory");
}
__device__ __forceinline__ void cpa_wait_all() {
    asm volatile("cp.async.wait_group 0;\n" ::: "memory");
}

__global__ __launch_bounds__(128, 4)
void involution2d_kernel(const float* __restrict__ input,
                         const float* __restrict__ weight,
                         const float* __restrict__ bias,
                         float* __restrict__ out)
{
    __shared__ float tile[2 * STAGE_CH * PLANE];   // double-buffered 2-ch stage
    __shared__ float sbias[64];

    const int tx  = threadIdx.x;            // 0..31
    const int ty  = threadIdx.y;            // 0..3
    const int tid = ty * 32 + tx;

    int bid = blockIdx.x;
    const int wt = bid & 1;  bid >>= 1;
    const int ht = bid & 7;  bid >>= 3;
    const int g  = bid & 3;  bid >>= 2;
    const int b  = bid;

    const int w0g = wt * TILE_W;
    const int h0g = ht * TILE_H;
    const int oy0 = ty * 2;
    const int ho0 = h0g + oy0;
    const int wo  = w0g + tx;

    if (tid < 64) sbias[tid] = bias[g * 64 + tid];

    // ---- weights for this thread's 2 output rows: 98 regs, read once ----
    float wr0[49], wr1[49];
    {
        const float* wp = weight + ((size_t)(b * 4 + g) * 49) * 4096 + ho0 * 64 + wo;
        #pragma unroll
        for (int k = 0; k < 49; ++k) {
            wr0[k] = wp[k * 4096];
            wr1[k] = wp[k * 4096 + 64];
        }
    }

    const float* inb  = input + (b * 256 + g * 64) * 4096;
    float*       outb = out   + (b * 256 + g * 64) * 4096;

    // ---- staged-load addressing (constant across channels) ----
    unsigned sdst[NSTAGE];
    int      goff[NSTAGE];
    bool     okm [NSTAGE];
    const unsigned sbase = (unsigned)__cvta_generic_to_shared(&tile[0]);
    #pragma unroll
    for (int k = 0; k < NSTAGE; ++k) {
        int i  = tid + k * 128;
        int r  = i / SW;
        int cc = i - r * SW;
        int gh = h0g - 3 + r;
        int gw = w0g - 3 + cc;
        bool valid = (i < SH * SW);
        bool ib    = ((unsigned)gh < 64u) && ((unsigned)gw < 64u);
        okm [k] = valid && ib;
        goff[k] = gh * 64 + gw;
        sdst[k] = sbase + (unsigned)(r * SWP + cc) * 4u;
        if (valid && !ib) {
            // halo: constant zero across all channels; write once, all planes
            #pragma unroll
            for (int p = 0; p < 2 * STAGE_CH; ++p)
                tile[p * PLANE + r * SWP + cc] = 0.0f;
        }
    }

    const unsigned BUFB = (unsigned)(STAGE_CH * PLANE * 4);  // bytes per buffer

    // ---- prologue: stage 0 -> buffer 0 ----
    #pragma unroll
    for (int c = 0; c < STAGE_CH; ++c)
        #pragma unroll
        for (int k = 0; k < NSTAGE; ++k)
            if (okm[k]) cpa4(sdst[k] + c * (PLANE * 4), inb + c * 4096 + goff[k]);
    cpa_commit();

    for (int s = 0; s < NSTAGES; ++s) {
        cpa_wait_all();          // stage s data landed (own ops)
        __syncthreads();         // all threads: data visible + prev compute done

        // issue stage s+1 into the other buffer (overlaps with compute below)
        if (s + 1 < NSTAGES) {
            const float* gsrc = inb + (size_t)(s + 1) * (STAGE_CH * 4096);
            const unsigned bo = ((s + 1) & 1) * BUFB;
            #pragma unroll
            for (int c = 0; c < STAGE_CH; ++c)
                #pragma unroll
                for (int k = 0; k < NSTAGE; ++k)
                    if (okm[k]) cpa4(sdst[k] + bo + c * (PLANE * 4), gsrc + c * 4096 + goff[k]);
        }
        cpa_commit();

        // ---- compute the 2 channels of stage s ----
        const float* bufp = &tile[(s & 1) * STAGE_CH * PLANE];
        #pragma unroll
        for (int c = 0; c < STAGE_CH; ++c) {
            const float* plane = bufp + c * PLANE;
            float acc0 = 0.0f, acc1 = 0.0f;
            #pragma unroll
            for (int r = 0; r < 8; ++r) {
                float x[7];
                const float* row = plane + (oy0 + r) * SWP + tx;
                #pragma unroll
                for (int j = 0; j < 7; ++j) x[j] = row[j];
                if (r < 7) {
                    #pragma unroll
                    for (int j = 0; j < 7; ++j) acc0 += x[j] * wr0[r * 7 + j];
                }
                if (r >= 1) {
                    #pragma unroll
                    for (int j = 0; j < 7; ++j) acc1 += x[j] * wr1[(r - 1) * 7 + j];
                }
            }
            const int ch = s * STAGE_CH + c;
            const float bv = sbias[ch];
            float* op = outb + ch * 4096 + ho0 * 64 + wo;
            op[0]  = acc0 + bv;
            op[64] = acc1 + bv;
        }
    }
}

extern "C" void kernel_launch(void* const* d_in, const int* in_sizes, int n_in,
                              void* d_out, int out_size)
{
    const float* input  = (const float*)d_in[0];
    const float* weight = (const float*)d_in[1];
    const float* bias   = (const float*)d_in[2];
    float*       out    = (float*)d_out;

    dim3 block(32, 4, 1);
    dim3 grid(8 * 4 * 8 * 2, 1, 1);   // B * G * Htiles * Wtiles = 512
    involution2d_kernel<<<grid, block>>>(input, weight, bias, out);
}